// round 14
// baseline (speedup 1.0000x reference)
#include <cuda_runtime.h>
#include <cstdint>

#define N_NODES 50000
#define N_EDGES 600000
#define F_IN    128
#define HID     128
#define N_CLS   40

typedef unsigned long long ull;

// ---------------- scratch (device globals; no runtime alloc) ----------------
__device__ float g_sumx[(size_t)N_NODES * F_IN];   // scatter-add of x
__device__ float g_h[(size_t)N_NODES * HID];       // layer-1 output
__device__ float g_a2[(size_t)N_NODES * N_CLS];    // h @ w2_l
__device__ float g_r2[(size_t)N_NODES * N_CLS];    // h @ w2_r
__device__ float g_sum2[(size_t)N_NODES * N_CLS];  // scatter-add of a2
__device__ float g_cnt[N_NODES];
__device__ int   g_src32[N_EDGES];                 // int32 indices (packed)
__device__ int   g_dst32[N_EDGES];
__device__ int   g_is64;                           // edge_index dtype flag

// ---------------- f32x2 packed-FMA helpers (PTX-only on sm_103a) -------------
__device__ __forceinline__ ull pack2(float lo, float hi) {
    ull r; asm("mov.b64 %0, {%1, %2};" : "=l"(r) : "f"(lo), "f"(hi)); return r;
}
__device__ __forceinline__ void unpack2(ull v, float& lo, float& hi) {
    asm("mov.b64 {%0, %1}, %2;" : "=f"(lo), "=f"(hi) : "l"(v));
}
__device__ __forceinline__ ull ffma2(ull a, ull b, ull c) {
    ull d; asm("fma.rn.f32x2 %0, %1, %2, %3;" : "=l"(d) : "l"(a), "l"(b), "l"(c));
    return d;
}

// ---------------- edge_index dtype detection + pack --------------------------
// JAX without x64 silently yields int32 even when int64 is requested, so the
// buffer may be either. True int64 indices (< 50000) have zero high words; an
// int32 layout read as 8-byte words has a random index in the high word
// (nonzero w.p. 1-1/50000 per word). 64 words decide with certainty.
__global__ void detect_kernel(const void* __restrict__ eidx) {
    const ull* p = (const ull*)eidx;
    int is64 = 1;
    for (int i = 0; i < 64; i++)
        if ((p[i] >> 32) != 0ull) { is64 = 0; break; }
    g_is64 = is64;
}

__global__ void pack_idx_kernel(const void* __restrict__ eidx) {
    int e = blockIdx.x * blockDim.x + threadIdx.x;
    if (e >= N_EDGES) return;
    if (g_is64) {
        const long long* p = (const long long*)eidx;
        g_src32[e] = (int)p[e];
        g_dst32[e] = (int)p[e + N_EDGES];
    } else {
        const int* p = (const int*)eidx;
        g_src32[e] = p[e];
        g_dst32[e] = p[e + N_EDGES];
    }
}

// ---------------- GEMM (templated tile, microtile 4x8, f32x2) ----------------
// Double-buffered static smem + register staging:
//   LDG(next tile) || compute(cur buf), STS(next buf), one sync per tile.
// N, K compile-time; N == BNt exactly for both layers (guards elided).
// LAYER==1 <1,64,128,256,128,256>: A=[sumx*inv | x] (K-concat), B=[w1l;w1r]
//                                  (K-concat). C0 = relu(acc + b1).
// LAYER==2 <2,64, 80,160, 80,128>: A=h, B=[w2l|w2r] (N-concat at 40).
//                                  C split: cols<40 -> a2, else r2 (ld 40).
#define BK 32
#define TM 4
#define TN 8

template <int LAYER, int BMt, int BNt, int THREADS, int Nt, int Kt>
__global__ __launch_bounds__(THREADS) void gemm_kernel(
    const float* __restrict__ A0,   // L1: sumx   L2: h
    const float* __restrict__ A1,   // L1: x      L2: unused
    const float* __restrict__ cnt,  // L1 only
    const float* __restrict__ B0,   // L1: w1l    L2: w2l
    const float* __restrict__ B1,   // L1: w1r    L2: w2r
    const float* __restrict__ bias, // L1: b1     L2: unused
    float* __restrict__ C0,
    float* __restrict__ C1,         // L2: r2
    int M) {
    constexpr int TXC = BNt / TN;                      // 16 / 10
    constexpr int TYC = BMt / TM;                      // 16
    static_assert(TXC * TYC == THREADS, "geometry");
    static_assert(Nt == BNt, "exact-fit tile: all column guards elided");
    constexpr int AS_BUF = BK * BMt;
    constexpr int BS_BUF = BK * BNt;
    constexpr int NA4 = BMt * (BK / 4);
    constexpr int NB4 = BK * (BNt / 4);
    constexpr int NLD_A = (NA4 + THREADS - 1) / THREADS;
    constexpr int NLD_B = (NB4 + THREADS - 1) / THREADS;
    static_assert(NB4 % THREADS == 0, "B loader exact");
    constexpr int NUM_T = Kt / BK;
    static_assert(Kt % BK == 0, "K multiple of BK");

    __shared__ __align__(16) float As[2 * AS_BUF];  // As[buf*AS_BUF + k*BMt + m]
    __shared__ __align__(16) float Bs[2 * BS_BUF];  // Bs[buf*BS_BUF + k*BNt + n]

    int tid = threadIdx.x;
    int tx = tid % TXC;
    int ty = tid / TXC;
    int rowBase = blockIdx.x * BMt;

    ull acc2[TM][TN / 2];
#pragma unroll
    for (int i = 0; i < TM; i++)
#pragma unroll
        for (int j = 0; j < TN / 2; j++) acc2[i][j] = pack2(0.f, 0.f);

    float4 aReg[NLD_A], bReg[NLD_B];

    auto loadA = [&](int k0) {
#pragma unroll
        for (int j = 0; j < NLD_A; j++) {
            int i = tid + j * THREADS;
            float4 v = make_float4(0.f, 0.f, 0.f, 0.f);
            if (i < NA4) {
                int r  = i / (BK / 4);
                int c4 = i % (BK / 4);
                int gr = rowBase + r;
                int kk = k0 + c4 * 4;
                if (gr < M) {
                    if (LAYER == 1) {
                        if (kk < F_IN) {
                            float4 s = *(const float4*)&A0[(size_t)gr * F_IN + kk];
                            float inv = 1.0f / fmaxf(__ldg(&cnt[gr]), 1.0f);
                            v.x = s.x * inv; v.y = s.y * inv;
                            v.z = s.z * inv; v.w = s.w * inv;
                        } else {
                            v = *(const float4*)&A1[(size_t)gr * F_IN + (kk - F_IN)];
                        }
                    } else {
                        v = *(const float4*)&A0[(size_t)gr * Kt + kk];
                    }
                }
            }
            aReg[j] = v;
        }
    };
    auto loadB = [&](int k0) {
#pragma unroll
        for (int j = 0; j < NLD_B; j++) {
            int i = tid + j * THREADS;
            int r  = i / (BNt / 4);
            int c4 = i % (BNt / 4);
            int gc = c4 * 4;
            int kr = k0 + r;
            float4 v;
            if (LAYER == 1) {
                v = (kr < F_IN)
                    ? *(const float4*)&B0[(size_t)kr * HID + gc]
                    : *(const float4*)&B1[(size_t)(kr - F_IN) * HID + gc];
            } else {
                v = (gc < N_CLS)
                    ? *(const float4*)&B0[(size_t)kr * N_CLS + gc]
                    : *(const float4*)&B1[(size_t)kr * N_CLS + (gc - N_CLS)];
            }
            bReg[j] = v;
        }
    };
    auto stsTiles = [&](int buf) {
        float* a = As + buf * AS_BUF;
#pragma unroll
        for (int j = 0; j < NLD_A; j++) {
            int i = tid + j * THREADS;
            if (i < NA4) {
                int r  = i / (BK / 4);
                int c4 = i % (BK / 4);
                a[(c4 * 4 + 0) * BMt + r] = aReg[j].x;
                a[(c4 * 4 + 1) * BMt + r] = aReg[j].y;
                a[(c4 * 4 + 2) * BMt + r] = aReg[j].z;
                a[(c4 * 4 + 3) * BMt + r] = aReg[j].w;
            }
        }
        float* b = Bs + buf * BS_BUF;
#pragma unroll
        for (int j = 0; j < NLD_B; j++) {
            int i = tid + j * THREADS;
            int r  = i / (BNt / 4);
            int c4 = i % (BNt / 4);
            *(float4*)&b[r * BNt + c4 * 4] = bReg[j];
        }
    };

    // prologue: tile 0 -> buffer 0
    loadA(0); loadB(0);
    stsTiles(0);
    __syncthreads();

    int buf = 0;
#pragma unroll 1   // keep rolled: full unroll would blow the 32KB L1.5 I$
    for (int t = 0; t < NUM_T; t++) {
        bool more = (t + 1) < NUM_T;
        if (more) { loadA((t + 1) * BK); loadB((t + 1) * BK); }  // overlap compute

        const float* aB = As + buf * AS_BUF;
        const float* bB = Bs + buf * BS_BUF;
#pragma unroll
        for (int k = 0; k < BK; k++) {
            float4 a4 = *(const float4*)&aB[k * BMt + ty * TM];  // LDS.128, bcast
            ull a2[TM];
            a2[0] = pack2(a4.x, a4.x);
            a2[1] = pack2(a4.y, a4.y);
            a2[2] = pack2(a4.z, a4.z);
            a2[3] = pack2(a4.w, a4.w);
            const ull* bp = (const ull*)&bB[k * BNt + tx * TN];  // 4x LDS.64
            ull b2[TN / 2];
#pragma unroll
            for (int j = 0; j < TN / 2; j++) b2[j] = bp[j];
#pragma unroll
            for (int i = 0; i < TM; i++)
#pragma unroll
                for (int j = 0; j < TN / 2; j++)
                    acc2[i][j] = ffma2(a2[i], b2[j], acc2[i][j]);
        }

        if (more) stsTiles(buf ^ 1);
        __syncthreads();
        buf ^= 1;
    }

    // epilogue (no column guards: Nt == BNt)
#pragma unroll
    for (int i = 0; i < TM; i++) {
        int gr = rowBase + ty * TM + i;
        if (gr >= M) continue;
#pragma unroll
        for (int j = 0; j < TN / 2; j += 2) {
            int gc = tx * TN + j * 2;
            float v0, v1, v2, v3;
            unpack2(acc2[i][j],     v0, v1);
            unpack2(acc2[i][j + 1], v2, v3);
            if (LAYER == 1) {
                float4 bb = *(const float4*)&bias[gc];
                float4 o = make_float4(fmaxf(v0 + bb.x, 0.f),
                                       fmaxf(v1 + bb.y, 0.f),
                                       fmaxf(v2 + bb.z, 0.f),
                                       fmaxf(v3 + bb.w, 0.f));
                *(float4*)&C0[(size_t)gr * HID + gc] = o;
            } else {
                float4 o = make_float4(v0, v1, v2, v3);
                if (gc < N_CLS) {
                    *(float4*)&C0[(size_t)gr * N_CLS + gc] = o;
                } else {
                    *(float4*)&C1[(size_t)gr * N_CLS + (gc - N_CLS)] = o;
                }
            }
        }
    }
}

// ---------------- scatter 1: warp-per-edge + degree count --------------------
// out[dst] += A[src], rows of NF4*4 floats; one thread per (edge,float4).
// NF4=32: a warp covers one edge; int32 src/dst loads are warp-uniform.
template <int NF4>
__global__ void scatter_kernel(const float* __restrict__ A,
                               const int* __restrict__ src,
                               const int* __restrict__ dst,
                               float* __restrict__ out,
                               float* __restrict__ cnt) {
    long long i = (long long)blockIdx.x * blockDim.x + threadIdx.x;
    long long total = (long long)N_EDGES * NF4;
    if (i >= total) return;
    int e = (int)(i / NF4);
    int q = (int)(i % NF4);
    int s = __ldg(&src[e]);
    int d = __ldg(&dst[e]);
    float4 v = *(const float4*)&A[(size_t)s * (NF4 * 4) + q * 4];
    float* o = &out[(size_t)d * (NF4 * 4) + q * 4];
    asm volatile("red.global.add.v4.f32 [%0], {%1,%2,%3,%4};"
                 :: "l"(o), "f"(v.x), "f"(v.y), "f"(v.z), "f"(v.w)
                 : "memory");
    if (q == 0) {
        asm volatile("red.global.add.f32 [%0], %1;"
                     :: "l"(&cnt[d]), "f"(1.0f) : "memory");
    }
}

// ---------------- scatter 2: thread-per-edge (NF4 chunks serial) -------------
// One int32 index load per edge; NF4 independent RED.128s per thread (high MLP).
template <int NF4>
__global__ void scatter_edge_kernel(const float* __restrict__ A,
                                    const int* __restrict__ src,
                                    const int* __restrict__ dst,
                                    float* __restrict__ out) {
    int e = blockIdx.x * blockDim.x + threadIdx.x;
    if (e >= N_EDGES) return;
    int s = __ldg(&src[e]);
    int d = __ldg(&dst[e]);
    const float* a = &A[(size_t)s * (NF4 * 4)];
    float* o = &out[(size_t)d * (NF4 * 4)];
#pragma unroll
    for (int q = 0; q < NF4; q++) {
        float4 v = *(const float4*)&a[q * 4];
        asm volatile("red.global.add.v4.f32 [%0], {%1,%2,%3,%4};"
                     :: "l"(&o[q * 4]), "f"(v.x), "f"(v.y), "f"(v.z), "f"(v.w)
                     : "memory");
    }
}

// ---------------- final combine (float4): out = sum2/cnt + r2 + b2 -----------
#define NQ4 (N_CLS / 4)   // 10
__global__ __launch_bounds__(256) void combine2_kernel(const float* __restrict__ b2,
                                                       float* __restrict__ out) {
    int idx = blockIdx.x * blockDim.x + threadIdx.x;
    if (idx >= N_NODES * NQ4) return;
    int node = idx / NQ4;
    int q4   = idx % NQ4;
    float inv = 1.0f / fmaxf(__ldg(&g_cnt[node]), 1.0f);
    size_t off = (size_t)node * N_CLS + q4 * 4;
    float4 s = *(const float4*)&g_sum2[off];
    float4 r = *(const float4*)&g_r2[off];
    float4 b = __ldg((const float4*)&b2[q4 * 4]);
    float4 o;
    o.x = fmaf(s.x, inv, r.x + b.x);
    o.y = fmaf(s.y, inv, r.y + b.y);
    o.z = fmaf(s.z, inv, r.z + b.z);
    o.w = fmaf(s.w, inv, r.w + b.w);
    *(float4*)&out[off] = o;
}

// ---------------- launch ----------------
extern "C" void kernel_launch(void* const* d_in, const int* in_sizes, int n_in,
                              void* d_out, int out_size) {
    const float* x    = (const float*)d_in[0];
    const void*  eidx = d_in[1];                 // int64 OR int32 (JAX x64 off)
    const float* w1l  = (const float*)d_in[2];
    const float* w1r  = (const float*)d_in[3];
    const float* b1   = (const float*)d_in[4];
    const float* w2l  = (const float*)d_in[5];
    const float* w2r  = (const float*)d_in[6];
    const float* b2   = (const float*)d_in[7];
    float* out = (float*)d_out;

    float *sumx, *h, *a2, *r2, *sum2, *cnt;
    int *src32, *dst32;
    cudaGetSymbolAddress((void**)&sumx,  g_sumx);
    cudaGetSymbolAddress((void**)&h,     g_h);
    cudaGetSymbolAddress((void**)&a2,    g_a2);
    cudaGetSymbolAddress((void**)&r2,    g_r2);
    cudaGetSymbolAddress((void**)&sum2,  g_sum2);
    cudaGetSymbolAddress((void**)&cnt,   g_cnt);
    cudaGetSymbolAddress((void**)&src32, g_src32);
    cudaGetSymbolAddress((void**)&dst32, g_dst32);

    cudaMemsetAsync(sumx, 0, (size_t)N_NODES * F_IN * sizeof(float), 0);
    cudaMemsetAsync(sum2, 0, (size_t)N_NODES * N_CLS * sizeof(float), 0);
    cudaMemsetAsync(cnt,  0, (size_t)N_NODES * sizeof(float), 0);

    // dtype sniff + int32 pack (handles int64 and int32 edge_index layouts)
    detect_kernel<<<1, 1>>>(eidx);
    pack_idx_kernel<<<(N_EDGES + 255) / 256, 256>>>(eidx);

    // scatter raw x -> sumx; degree count fused (NF4=32: warp-per-edge)
    {
        long long total = (long long)N_EDGES * (F_IN / 4);
        scatter_kernel<F_IN / 4><<<(int)((total + 255) / 256), 256>>>(
            x, src32, dst32, sumx, cnt);
    }

    // layer 1: h = relu([sumx*inv | x] @ [w1l ; w1r] + b1)  (M=50000, N=128, K=256)
    {
        dim3 grid((N_NODES + 63) / 64, 1);
        gemm_kernel<1, 64, 128, 256, 128, 256><<<grid, 256>>>(
            sumx, x, cnt, w1l, w1r, b1, h, nullptr, N_NODES);
    }

    // layer 2: [a2|r2] = h @ [w2l | w2r]   (M=50000, N=80, K=128) — exact tile
    {
        dim3 grid((N_NODES + 63) / 64, 1);
        gemm_kernel<2, 64, 80, 160, 80, 128><<<grid, 160>>>(
            h, nullptr, nullptr, w2l, w2r, nullptr, a2, r2, N_NODES);
    }

    // scatter a2 -> sum2 (thread-per-edge, 10 RED.128 each)
    scatter_edge_kernel<N_CLS / 4><<<(N_EDGES + 255) / 256, 256>>>(
        a2, src32, dst32, sum2);

    combine2_kernel<<<(N_NODES * NQ4 + 255) / 256, 256>>>(b2, out);
}

// round 16
// speedup vs baseline: 1.2902x; 1.2902x over previous
#include <cuda_runtime.h>
#include <cstdint>

#define N_NODES 50000
#define N_EDGES 600000
#define F_IN    128
#define HID     128
#define N_CLS   40

typedef unsigned long long ull;

// ---------------- scratch (device globals; no runtime alloc) ----------------
__device__ float g_sumx[(size_t)N_NODES * F_IN];   // scatter-add of x
__device__ float g_h[(size_t)N_NODES * HID];       // layer-1 output
__device__ float g_a2[(size_t)N_NODES * N_CLS];    // h @ w2_l
__device__ float g_r2[(size_t)N_NODES * N_CLS];    // h @ w2_r
__device__ float g_sum2[(size_t)N_NODES * N_CLS];  // scatter-add of a2
__device__ float g_cnt[N_NODES];
__device__ int   g_src32[N_EDGES];                 // int32 indices (packed)
__device__ int   g_dst32[N_EDGES];
__device__ int   g_is64;                           // edge_index dtype flag

// ---------------- f32x2 packed-FMA helpers (PTX-only on sm_103a) -------------
__device__ __forceinline__ ull pack2(float lo, float hi) {
    ull r; asm("mov.b64 %0, {%1, %2};" : "=l"(r) : "f"(lo), "f"(hi)); return r;
}
__device__ __forceinline__ void unpack2(ull v, float& lo, float& hi) {
    asm("mov.b64 {%0, %1}, %2;" : "=f"(lo), "=f"(hi) : "l"(v));
}
__device__ __forceinline__ ull ffma2(ull a, ull b, ull c) {
    ull d; asm("fma.rn.f32x2 %0, %1, %2, %3;" : "=l"(d) : "l"(a), "l"(b), "l"(c));
    return d;
}

// ---------------- edge_index dtype detection + pack --------------------------
// JAX without x64 silently yields int32 even when int64 is requested, so the
// buffer may be either. True int64 indices (< 50000) have zero high words; an
// int32 layout read as 8-byte words has a random index in the high word.
__global__ void detect_kernel(const void* __restrict__ eidx) {
    const ull* p = (const ull*)eidx;
    int is64 = 1;
    for (int i = 0; i < 64; i++)
        if ((p[i] >> 32) != 0ull) { is64 = 0; break; }
    g_is64 = is64;
}

__global__ void pack_idx_kernel(const void* __restrict__ eidx) {
    int e = blockIdx.x * blockDim.x + threadIdx.x;
    if (e >= N_EDGES) return;
    if (g_is64) {
        const long long* p = (const long long*)eidx;
        g_src32[e] = (int)p[e];
        g_dst32[e] = (int)p[e + N_EDGES];
    } else {
        const int* p = (const int*)eidx;
        g_src32[e] = p[e];
        g_dst32[e] = p[e + N_EDGES];
    }
}

// ---------------- GEMM (templated tile, microtile 4x8, f32x2) ----------------
// Double-buffered static smem + register staging.
// B fragment per thread: TWO float4 groups at cols tx*4 and BNt/2 + tx*4.
// Lane stride 16B = 4 banks -> 16 lanes cover all 32 banks in 2 phases:
// conflict-free (round-14 ncu showed L1=81.5% from the old 4-way-conflict
// tx*8 stride). 2x LDS.128 instead of 4x LDS.64.
// LAYER==1 <1,64,128,256,128,256>: A=[sumx*inv | x] (K-concat), B=[w1l;w1r]
//                                  (K-concat). C0 = relu(acc + b1).
// LAYER==2 <2,64, 80,160, 80,128>: A=h, B=[w2l|w2r] (N-concat at 40).
//                                  Group0 (cols 0..39) -> a2, Group1 -> r2.
#define BK 32
#define TM 4
#define TN 8

template <int LAYER, int BMt, int BNt, int THREADS, int Nt, int Kt>
__global__ __launch_bounds__(THREADS) void gemm_kernel(
    const float* __restrict__ A0,   // L1: sumx   L2: h
    const float* __restrict__ A1,   // L1: x      L2: unused
    const float* __restrict__ cnt,  // L1 only
    const float* __restrict__ B0,   // L1: w1l    L2: w2l
    const float* __restrict__ B1,   // L1: w1r    L2: w2r
    const float* __restrict__ bias, // L1: b1     L2: unused
    float* __restrict__ C0,
    float* __restrict__ C1,         // L2: r2
    int M) {
    constexpr int TXC = BNt / TN;                      // 16 / 10
    constexpr int TYC = BMt / TM;                      // 16
    constexpr int HALF = BNt / 2;                      // 64 / 40
    static_assert(TXC * TYC == THREADS, "geometry");
    static_assert(Nt == BNt, "exact-fit tile");
    static_assert((HALF * 4) % 16 == 0, "group offset 16B-aligned");
    constexpr int AS_BUF = BK * BMt;
    constexpr int BS_BUF = BK * BNt;
    constexpr int NA4 = BMt * (BK / 4);
    constexpr int NB4 = BK * (BNt / 4);
    constexpr int NLD_A = (NA4 + THREADS - 1) / THREADS;
    constexpr int NLD_B = (NB4 + THREADS - 1) / THREADS;
    static_assert(NB4 % THREADS == 0, "B loader exact");
    constexpr int NUM_T = Kt / BK;
    static_assert(Kt % BK == 0, "K multiple of BK");

    __shared__ __align__(16) float As[2 * AS_BUF];  // As[buf*AS_BUF + k*BMt + m]
    __shared__ __align__(16) float Bs[2 * BS_BUF];  // Bs[buf*BS_BUF + k*BNt + n]

    int tid = threadIdx.x;
    int tx = tid % TXC;
    int ty = tid / TXC;
    int rowBase = blockIdx.x * BMt;

    // acc2[i][0..1] = group0 cols (tx*4 .. +3); acc2[i][2..3] = group1 cols
    ull acc2[TM][4];
#pragma unroll
    for (int i = 0; i < TM; i++)
#pragma unroll
        for (int j = 0; j < 4; j++) acc2[i][j] = pack2(0.f, 0.f);

    float4 aReg[NLD_A], bReg[NLD_B];

    auto loadA = [&](int k0) {
#pragma unroll
        for (int j = 0; j < NLD_A; j++) {
            int i = tid + j * THREADS;
            float4 v = make_float4(0.f, 0.f, 0.f, 0.f);
            if (i < NA4) {
                int r  = i / (BK / 4);
                int c4 = i % (BK / 4);
                int gr = rowBase + r;
                int kk = k0 + c4 * 4;
                if (gr < M) {
                    if (LAYER == 1) {
                        if (kk < F_IN) {
                            float4 s = *(const float4*)&A0[(size_t)gr * F_IN + kk];
                            float inv = 1.0f / fmaxf(__ldg(&cnt[gr]), 1.0f);
                            v.x = s.x * inv; v.y = s.y * inv;
                            v.z = s.z * inv; v.w = s.w * inv;
                        } else {
                            v = *(const float4*)&A1[(size_t)gr * F_IN + (kk - F_IN)];
                        }
                    } else {
                        v = *(const float4*)&A0[(size_t)gr * Kt + kk];
                    }
                }
            }
            aReg[j] = v;
        }
    };
    auto loadB = [&](int k0) {
#pragma unroll
        for (int j = 0; j < NLD_B; j++) {
            int i = tid + j * THREADS;
            int r  = i / (BNt / 4);
            int c4 = i % (BNt / 4);
            int gc = c4 * 4;
            int kr = k0 + r;
            float4 v;
            if (LAYER == 1) {
                v = (kr < F_IN)
                    ? *(const float4*)&B0[(size_t)kr * HID + gc]
                    : *(const float4*)&B1[(size_t)(kr - F_IN) * HID + gc];
            } else {
                v = (gc < N_CLS)
                    ? *(const float4*)&B0[(size_t)kr * N_CLS + gc]
                    : *(const float4*)&B1[(size_t)kr * N_CLS + (gc - N_CLS)];
            }
            bReg[j] = v;
        }
    };
    auto stsTiles = [&](int buf) {
        float* a = As + buf * AS_BUF;
#pragma unroll
        for (int j = 0; j < NLD_A; j++) {
            int i = tid + j * THREADS;
            if (i < NA4) {
                int r  = i / (BK / 4);
                int c4 = i % (BK / 4);
                a[(c4 * 4 + 0) * BMt + r] = aReg[j].x;
                a[(c4 * 4 + 1) * BMt + r] = aReg[j].y;
                a[(c4 * 4 + 2) * BMt + r] = aReg[j].z;
                a[(c4 * 4 + 3) * BMt + r] = aReg[j].w;
            }
        }
        float* b = Bs + buf * BS_BUF;
#pragma unroll
        for (int j = 0; j < NLD_B; j++) {
            int i = tid + j * THREADS;
            int r  = i / (BNt / 4);
            int c4 = i % (BNt / 4);
            *(float4*)&b[r * BNt + c4 * 4] = bReg[j];
        }
    };

    // prologue: tile 0 -> buffer 0
    loadA(0); loadB(0);
    stsTiles(0);
    __syncthreads();

    int buf = 0;
#pragma unroll 1   // keep rolled: full unroll would blow the 32KB L1.5 I$
    for (int t = 0; t < NUM_T; t++) {
        bool more = (t + 1) < NUM_T;
        if (more) { loadA((t + 1) * BK); loadB((t + 1) * BK); }  // overlap compute

        const float* aB = As + buf * AS_BUF;
        const float* bB = Bs + buf * BS_BUF;
#pragma unroll
        for (int k = 0; k < BK; k++) {
            float4 a4 = *(const float4*)&aB[k * BMt + ty * TM];  // LDS.128, bcast
            ull a2[TM];
            a2[0] = pack2(a4.x, a4.x);
            a2[1] = pack2(a4.y, a4.y);
            a2[2] = pack2(a4.z, a4.z);
            a2[3] = pack2(a4.w, a4.w);
            // B: two conflict-free LDS.128 (lane stride 16B)
            ulonglong2 bg0 = *(const ulonglong2*)&bB[k * BNt + tx * 4];
            ulonglong2 bg1 = *(const ulonglong2*)&bB[k * BNt + HALF + tx * 4];
            ull b2[4] = {bg0.x, bg0.y, bg1.x, bg1.y};
#pragma unroll
            for (int i = 0; i < TM; i++)
#pragma unroll
                for (int j = 0; j < 4; j++)
                    acc2[i][j] = ffma2(a2[i], b2[j], acc2[i][j]);
        }

        if (more) stsTiles(buf ^ 1);
        __syncthreads();
        buf ^= 1;
    }

    // epilogue: group0 at cols tx*4, group1 at cols HALF + tx*4
#pragma unroll
    for (int i = 0; i < TM; i++) {
        int gr = rowBase + ty * TM + i;
        if (gr >= M) continue;
        float g0a, g0b, g0c, g0d, g1a, g1b, g1c, g1d;
        unpack2(acc2[i][0], g0a, g0b);
        unpack2(acc2[i][1], g0c, g0d);
        unpack2(acc2[i][2], g1a, g1b);
        unpack2(acc2[i][3], g1c, g1d);
        if (LAYER == 1) {
            int gc0 = tx * 4, gc1 = HALF + tx * 4;
            float4 bb0 = *(const float4*)&bias[gc0];
            float4 bb1 = *(const float4*)&bias[gc1];
            *(float4*)&C0[(size_t)gr * HID + gc0] =
                make_float4(fmaxf(g0a + bb0.x, 0.f), fmaxf(g0b + bb0.y, 0.f),
                            fmaxf(g0c + bb0.z, 0.f), fmaxf(g0d + bb0.w, 0.f));
            *(float4*)&C0[(size_t)gr * HID + gc1] =
                make_float4(fmaxf(g1a + bb1.x, 0.f), fmaxf(g1b + bb1.y, 0.f),
                            fmaxf(g1c + bb1.z, 0.f), fmaxf(g1d + bb1.w, 0.f));
        } else {
            // group0 = a2 cols (0..39), group1 = r2 cols (40..79) exactly
            *(float4*)&C0[(size_t)gr * N_CLS + tx * 4] =
                make_float4(g0a, g0b, g0c, g0d);
            *(float4*)&C1[(size_t)gr * N_CLS + tx * 4] =
                make_float4(g1a, g1b, g1c, g1d);
        }
    }
}

// ---------------- scatter 1: warp-per-edge + degree count --------------------
template <int NF4>
__global__ void scatter_kernel(const float* __restrict__ A,
                               const int* __restrict__ src,
                               const int* __restrict__ dst,
                               float* __restrict__ out,
                               float* __restrict__ cnt) {
    long long i = (long long)blockIdx.x * blockDim.x + threadIdx.x;
    long long total = (long long)N_EDGES * NF4;
    if (i >= total) return;
    int e = (int)(i / NF4);
    int q = (int)(i % NF4);
    int s = __ldg(&src[e]);
    int d = __ldg(&dst[e]);
    float4 v = *(const float4*)&A[(size_t)s * (NF4 * 4) + q * 4];
    float* o = &out[(size_t)d * (NF4 * 4) + q * 4];
    asm volatile("red.global.add.v4.f32 [%0], {%1,%2,%3,%4};"
                 :: "l"(o), "f"(v.x), "f"(v.y), "f"(v.z), "f"(v.w)
                 : "memory");
    if (q == 0) {
        asm volatile("red.global.add.f32 [%0], %1;"
                     :: "l"(&cnt[d]), "f"(1.0f) : "memory");
    }
}

// ---------------- scatter 2: thread-per-edge (NF4 chunks serial) -------------
template <int NF4>
__global__ void scatter_edge_kernel(const float* __restrict__ A,
                                    const int* __restrict__ src,
                                    const int* __restrict__ dst,
                                    float* __restrict__ out) {
    int e = blockIdx.x * blockDim.x + threadIdx.x;
    if (e >= N_EDGES) return;
    int s = __ldg(&src[e]);
    int d = __ldg(&dst[e]);
    const float* a = &A[(size_t)s * (NF4 * 4)];
    float* o = &out[(size_t)d * (NF4 * 4)];
#pragma unroll
    for (int q = 0; q < NF4; q++) {
        float4 v = *(const float4*)&a[q * 4];
        asm volatile("red.global.add.v4.f32 [%0], {%1,%2,%3,%4};"
                     :: "l"(&o[q * 4]), "f"(v.x), "f"(v.y), "f"(v.z), "f"(v.w)
                     : "memory");
    }
}

// ---------------- final combine (float4): out = sum2/cnt + r2 + b2 -----------
#define NQ4 (N_CLS / 4)   // 10
__global__ __launch_bounds__(256) void combine2_kernel(const float* __restrict__ b2,
                                                       float* __restrict__ out) {
    int idx = blockIdx.x * blockDim.x + threadIdx.x;
    if (idx >= N_NODES * NQ4) return;
    int node = idx / NQ4;
    int q4   = idx % NQ4;
    float inv = 1.0f / fmaxf(__ldg(&g_cnt[node]), 1.0f);
    size_t off = (size_t)node * N_CLS + q4 * 4;
    float4 s = *(const float4*)&g_sum2[off];
    float4 r = *(const float4*)&g_r2[off];
    float4 b = __ldg((const float4*)&b2[q4 * 4]);
    float4 o;
    o.x = fmaf(s.x, inv, r.x + b.x);
    o.y = fmaf(s.y, inv, r.y + b.y);
    o.z = fmaf(s.z, inv, r.z + b.z);
    o.w = fmaf(s.w, inv, r.w + b.w);
    *(float4*)&out[off] = o;
}

// ---------------- launch ----------------
extern "C" void kernel_launch(void* const* d_in, const int* in_sizes, int n_in,
                              void* d_out, int out_size) {
    const float* x    = (const float*)d_in[0];
    const void*  eidx = d_in[1];                 // int64 OR int32 (JAX x64 off)
    const float* w1l  = (const float*)d_in[2];
    const float* w1r  = (const float*)d_in[3];
    const float* b1   = (const float*)d_in[4];
    const float* w2l  = (const float*)d_in[5];
    const float* w2r  = (const float*)d_in[6];
    const float* b2   = (const float*)d_in[7];
    float* out = (float*)d_out;

    float *sumx, *h, *a2, *r2, *sum2, *cnt;
    int *src32, *dst32;
    cudaGetSymbolAddress((void**)&sumx,  g_sumx);
    cudaGetSymbolAddress((void**)&h,     g_h);
    cudaGetSymbolAddress((void**)&a2,    g_a2);
    cudaGetSymbolAddress((void**)&r2,    g_r2);
    cudaGetSymbolAddress((void**)&sum2,  g_sum2);
    cudaGetSymbolAddress((void**)&cnt,   g_cnt);
    cudaGetSymbolAddress((void**)&src32, g_src32);
    cudaGetSymbolAddress((void**)&dst32, g_dst32);

    cudaMemsetAsync(sumx, 0, (size_t)N_NODES * F_IN * sizeof(float), 0);
    cudaMemsetAsync(sum2, 0, (size_t)N_NODES * N_CLS * sizeof(float), 0);
    cudaMemsetAsync(cnt,  0, (size_t)N_NODES * sizeof(float), 0);

    // dtype sniff + int32 pack (handles int64 and int32 edge_index layouts)
    detect_kernel<<<1, 1>>>(eidx);
    pack_idx_kernel<<<(N_EDGES + 255) / 256, 256>>>(eidx);

    // scatter raw x -> sumx; degree count fused (NF4=32: warp-per-edge)
    {
        long long total = (long long)N_EDGES * (F_IN / 4);
        scatter_kernel<F_IN / 4><<<(int)((total + 255) / 256), 256>>>(
            x, src32, dst32, sumx, cnt);
    }

    // layer 1: h = relu([sumx*inv | x] @ [w1l ; w1r] + b1)  (M=50000, N=128, K=256)
    {
        dim3 grid((N_NODES + 63) / 64, 1);
        gemm_kernel<1, 64, 128, 256, 128, 256><<<grid, 256>>>(
            sumx, x, cnt, w1l, w1r, b1, h, nullptr, N_NODES);
    }

    // layer 2: [a2|r2] = h @ [w2l | w2r]   (M=50000, N=80, K=128) — exact tile
    {
        dim3 grid((N_NODES + 63) / 64, 1);
        gemm_kernel<2, 64, 80, 160, 80, 128><<<grid, 160>>>(
            h, nullptr, nullptr, w2l, w2r, nullptr, a2, r2, N_NODES);
    }

    // scatter a2 -> sum2 (thread-per-edge, 10 RED.128 each)
    scatter_edge_kernel<N_CLS / 4><<<(N_EDGES + 255) / 256, 256>>>(
        a2, src32, dst32, sum2);

    combine2_kernel<<<(N_NODES * NQ4 + 255) / 256, 256>>>(b2, out);
}